// round 3
// baseline (speedup 1.0000x reference)
#include <cuda_runtime.h>
#include <cstdint>
#include <math.h>

#define TEXT 768
#define HID  256
#define BB   16
#define NN   4096
#define MROWS (BB*NN)

// ---------------- device scratch (no allocs allowed) ----------------
__device__ float g_WfT[TEXT*HID];   // [d][h] = (W1c @ Wc)^T, computed in fp64
__device__ float g_query[BB*HID];
__device__ float g_cvec[BB*HID];
__device__ float g_base[HID];
__device__ float g_Me[4*HID];
__device__ float g_vt[HID];
__device__ float g_vs[HID];
__device__ float g_wsem[HID];
__device__ float g_na[BB];
__device__ int   g_et64;

__device__ __forceinline__ float gelu_exact(float x) {
    return 0.5f * x * (1.0f + erff(x * 0.70710678118654752f));
}

// ---------------- dtype sniffer (kept; harmless) ----------------
__global__ void detect_et(const int* __restrict__ et) {
    int nz = 0;
    for (int i = 1; i < 4096; i += 2) nz += (et[i] != 0);
    g_et64 = (nz == 0) ? 1 : 0;
}

// ---------------- prep kernels: fp64 accumulation ----------------

// query[b][h] = Wq[h,:].center[b,:] + bq[h];  g_na[b] = max(||center_b||,1e-8)
__global__ void prep_query(const float* __restrict__ center,
                           const float* __restrict__ Wq,
                           const float* __restrict__ bq) {
    __shared__ float c[TEXT];
    __shared__ double red[HID];
    int b = blockIdx.x, t = threadIdx.x;
    for (int i = t; i < TEXT; i += HID) c[i] = center[b*TEXT + i];
    __syncthreads();
    double s = 0.0;
    for (int i = t; i < TEXT; i += HID) { double v = (double)c[i]; s += v*v; }
    red[t] = s; __syncthreads();
    for (int o = HID/2; o > 0; o >>= 1) { if (t < o) red[t] += red[t+o]; __syncthreads(); }
    if (t == 0) g_na[b] = fmaxf((float)sqrt(red[0]), 1e-8f);
    double acc = (double)bq[t];
    const float* wr = Wq + (size_t)t*TEXT;
    for (int d = 0; d < TEXT; d++) acc += (double)wr[d] * (double)c[d];
    g_query[b*HID + t] = (float)acc;
}

// per-h constants from W1 blocks (fp64)
__global__ void prep_small(const float* __restrict__ W1, const float* __restrict__ Wt,
                           const float* __restrict__ Ws, const float* __restrict__ bt,
                           const float* __restrict__ bs, const float* __restrict__ bc,
                           const float* __restrict__ b1, const float* __restrict__ Ee) {
    int h = threadIdx.x;
    const float* w1 = W1 + (size_t)h * 1281;
    double vt=0, vs=0, ut=0, us=0, wb=0;
    for (int k = 0; k < HID; k++) {
        double w_t = w1[768 + k], w_s = w1[1024 + k], w_c = w1[256 + k];
        vt += w_t * (double)Wt[k];
        ut += w_t * (double)bt[k];
        vs += w_s * (double)Ws[k];
        us += w_s * (double)bs[k];
        wb += w_c * (double)bc[k];
    }
    g_vt[h] = (float)vt; g_vs[h] = (float)vs; g_wsem[h] = w1[1280];
    g_base[h] = (float)(ut + us + wb + (double)b1[h]);
    for (int e = 0; e < 4; e++) {
        double m = 0;
        for (int k = 0; k < HID; k++) m += (double)w1[512 + k] * (double)Ee[e*HID + k];
        g_Me[e*HID + h] = (float)m;
    }
}

// cvec[b][h] = W1q[h,:].query[b,:] + base[h]   (fp64)
__global__ void prep_cvec(const float* __restrict__ W1) {
    __shared__ float q[HID];
    int b = blockIdx.x, h = threadIdx.x;
    q[h] = g_query[b*HID + h];
    __syncthreads();
    double acc = (double)g_base[h];
    const float* w1 = W1 + (size_t)h * 1281;
    for (int k = 0; k < HID; k++) acc += (double)w1[k] * (double)q[k];
    g_cvec[b*HID + h] = (float)acc;
}

// WfT[d][h] = sum_k Wc[k][d] * W1[h][256+k]    (fp64; 768 blocks x 256 thr, 50M DFMA)
__global__ void prep_wf(const float* __restrict__ Wc, const float* __restrict__ W1) {
    __shared__ float col[HID];
    int d = blockIdx.x, h = threadIdx.x;
    col[h] = Wc[(size_t)h*TEXT + d];
    __syncthreads();
    double acc = 0;
    const float* w1 = W1 + (size_t)h*1281 + 256;
    for (int k = 0; k < HID; k++) acc += (double)w1[k] * (double)col[k];
    g_WfT[(size_t)d*HID + h] = (float)acc;
}

// ---------------- main fused GEMM + epilogue ----------------
// 64 rows/block (single batch), all 256 H-cols, 256 threads.
// Two-level accumulation: per-16k-tile partials (f32x2) -> grand acc once per tile.
#define FMA2(acc, aa, bb) asm("fma.rn.f32x2 %0, %1, %2, %0;" : "+l"(acc) : "l"(aa), "l"(bb))
#define ADD2(acc, bb)     asm("add.rn.f32x2 %0, %0, %1;"     : "+l"(acc) : "l"(bb))

__global__ __launch_bounds__(256)
void main_kernel(const float* __restrict__ emb, const float* __restrict__ center,
                 const int* __restrict__ maskv, const int* __restrict__ etypes,
                 const float* __restrict__ yd, const float* __restrict__ cs,
                 const float* __restrict__ W2, const float* __restrict__ b2,
                 float* __restrict__ out_logits) {
    __shared__ __align__(16) float As[16][68];
    __shared__ __align__(16) float Bs[16][256];
    __shared__ float sh_cvec[HID], sh_vt[HID], sh_vs[HID], sh_wsem[HID], sh_W2[HID];
    __shared__ float sh_Me[4][HID];
    __shared__ float sh_c[TEXT];
    __shared__ float sh_dot[64], sh_nrm[64];
    __shared__ float sh_yd[64], sh_cs[64];
    __shared__ int   sh_et[64], sh_mask[64];

    int t = threadIdx.x;
    int r0 = blockIdx.x * 64;
    int b = r0 >> 12;
    int et64 = g_et64;

    {
        int i = t;
        sh_cvec[i] = g_cvec[b*HID + i];
        sh_vt[i] = g_vt[i]; sh_vs[i] = g_vs[i]; sh_wsem[i] = g_wsem[i]; sh_W2[i] = W2[i];
        for (int u = t; u < 4*HID; u += 256) sh_Me[u >> 8][u & 255] = g_Me[u];
        for (int u = t; u < TEXT; u += 256) sh_c[u] = center[b*TEXT + u];
        if (t < 64) {
            int grow = r0 + t;
            int e = et64 ? etypes[2*grow] : etypes[grow];
            sh_et[t] = e < 0 ? 0 : (e > 3 ? 3 : e);
            sh_yd[t] = yd[grow]; sh_cs[t] = cs[grow]; sh_mask[t] = maskv[grow];
        }
    }

    int ty = t >> 5, tx = t & 31;
    int lr = t >> 2, lc4 = t & 3;
    unsigned long long acc2[8][4] = {};   // grand accumulators (packed fp32 pairs)
    float dotA = 0.f, nrmA = 0.f;
    float na_b = g_na[b];
    float b2v = b2[0];

    for (int kk = 0; kk < TEXT; kk += 16) {
        float4 av = *(const float4*)(emb + (size_t)(r0 + lr)*TEXT + kk + lc4*4);
        As[lc4*4 + 0][lr] = av.x; As[lc4*4 + 1][lr] = av.y;
        As[lc4*4 + 2][lr] = av.z; As[lc4*4 + 3][lr] = av.w;
        #pragma unroll
        for (int j = 0; j < 4; j++) {
            int u = t + j*256; int kc = u >> 6, h4 = u & 63;
            ((float4*)&Bs[kc][0])[h4] = *(const float4*)(g_WfT + (size_t)(kk + kc)*HID + h4*4);
        }
        __syncthreads();

        if (t < 64) {
            #pragma unroll
            for (int kc = 0; kc < 16; kc++) {
                float v = As[kc][t];
                dotA = fmaf(v, sh_c[kk + kc], dotA);
                nrmA = fmaf(v, v, nrmA);
            }
        }

        // tile-local accumulators (reset each tile)
        unsigned long long t2[8][4] = {};
        #pragma unroll
        for (int kc = 0; kc < 16; kc++) {
            float4 a0 = *(const float4*)&As[kc][ty*8];
            float4 a1 = *(const float4*)&As[kc][ty*8 + 4];
            unsigned long long bp0 = *(const unsigned long long*)&Bs[kc][tx*2];
            unsigned long long bp1 = *(const unsigned long long*)&Bs[kc][tx*2 + 64];
            unsigned long long bp2 = *(const unsigned long long*)&Bs[kc][tx*2 + 128];
            unsigned long long bp3 = *(const unsigned long long*)&Bs[kc][tx*2 + 192];
            float avv[8] = {a0.x, a0.y, a0.z, a0.w, a1.x, a1.y, a1.z, a1.w};
            #pragma unroll
            for (int i = 0; i < 8; i++) {
                unsigned long long aa; unsigned int ai = __float_as_uint(avv[i]);
                asm("mov.b64 %0, {%1,%1};" : "=l"(aa) : "r"(ai));
                FMA2(t2[i][0], aa, bp0);
                FMA2(t2[i][1], aa, bp1);
                FMA2(t2[i][2], aa, bp2);
                FMA2(t2[i][3], aa, bp3);
            }
        }
        #pragma unroll
        for (int i = 0; i < 8; i++) {
            ADD2(acc2[i][0], t2[i][0]);
            ADD2(acc2[i][1], t2[i][1]);
            ADD2(acc2[i][2], t2[i][2]);
            ADD2(acc2[i][3], t2[i][3]);
        }
        __syncthreads();
    }

    if (t < 64) { sh_dot[t] = dotA; sh_nrm[t] = nrmA; }
    __syncthreads();

    #pragma unroll
    for (int i = 0; i < 8; i++) {
        int lrow = ty*8 + i;
        float sem = sh_dot[lrow] / (na_b * fmaxf(sqrtf(sh_nrm[lrow]), 1e-8f));
        float ydv = sh_yd[lrow], csv = sh_cs[lrow];
        const float* me = &sh_Me[sh_et[lrow]][0];
        float p = 0.f;
        #pragma unroll
        for (int j = 0; j < 4; j++) {
            unsigned int lo32, hi32;
            asm("mov.b64 {%0,%1}, %2;" : "=r"(lo32), "=r"(hi32) : "l"(acc2[i][j]));
            int c0 = tx*2 + j*64;
            float x0 = __uint_as_float(lo32) + sh_cvec[c0] + me[c0]
                     + ydv*sh_vt[c0] + csv*sh_vs[c0] + sem*sh_wsem[c0];
            p = fmaf(sh_W2[c0], gelu_exact(x0), p);
            int c1 = c0 + 1;
            float x1 = __uint_as_float(hi32) + sh_cvec[c1] + me[c1]
                     + ydv*sh_vt[c1] + csv*sh_vs[c1] + sem*sh_wsem[c1];
            p = fmaf(sh_W2[c1], gelu_exact(x1), p);
        }
        #pragma unroll
        for (int o = 16; o > 0; o >>= 1) p += __shfl_down_sync(0xffffffffu, p, o);
        if (tx == 0) {
            float lg = p + b2v;
            out_logits[r0 + lrow] = sh_mask[lrow] != 0 ? lg : -1.0e9f;
        }
    }
}

// ---------------- top-k: per-batch bitonic sort ----------------
__global__ void topk_kernel(const float* __restrict__ logits,
                            float* __restrict__ out_idx, float* __restrict__ out_val, int k) {
    __shared__ unsigned long long key[NN];
    int b = blockIdx.x, t = threadIdx.x;
    for (int i = t; i < NN; i += 512) {
        float f = logits[b*NN + i];
        unsigned u = __float_as_uint(f);
        u = (u & 0x80000000u) ? ~u : (u | 0x80000000u);
        key[i] = ((unsigned long long)(~u) << 32) | (unsigned)i;
    }
    __syncthreads();
    for (int size = 2; size <= NN; size <<= 1) {
        for (int stride = size >> 1; stride > 0; stride >>= 1) {
            for (int i = t; i < NN/2; i += 512) {
                int lo = ((i & ~(stride - 1)) << 1) | (i & (stride - 1));
                int hi = lo + stride;
                bool asc = ((lo & size) == 0);
                unsigned long long a = key[lo], c = key[hi];
                if ((a > c) == asc) { key[lo] = c; key[hi] = a; }
            }
            __syncthreads();
        }
    }
    if (t < k) {
        unsigned idx = (unsigned)(key[t] & 0xffffffffu);
        out_idx[b*k + t] = (float)idx;
        out_val[b*k + t] = logits[b*NN + idx];
    }
}

// ---------------- launch ----------------
extern "C" void kernel_launch(void* const* d_in, const int* in_sizes, int n_in,
                              void* d_out, int out_size) {
    const float* center = (const float*)d_in[0];
    const float* emb    = (const float*)d_in[1];
    const int*   maskv  = (const int*)d_in[2];
    const int*   etypes = (const int*)d_in[3];
    const float* yd     = (const float*)d_in[4];
    const float* cs     = (const float*)d_in[5];
    const float* Wq = (const float*)d_in[7];
    const float* bq = (const float*)d_in[8];
    const float* Wc = (const float*)d_in[9];
    const float* bc = (const float*)d_in[10];
    const float* Ee = (const float*)d_in[11];
    const float* Wt = (const float*)d_in[12];
    const float* bt = (const float*)d_in[13];
    const float* Ws = (const float*)d_in[14];
    const float* bs = (const float*)d_in[15];
    const float* W1 = (const float*)d_in[16];
    const float* b1 = (const float*)d_in[17];
    const float* W2 = (const float*)d_in[18];
    const float* b2 = (const float*)d_in[19];

    float* out = (float*)d_out;
    int k = (out_size - MROWS) / (2 * BB);
    if (k < 1 || k > NN) k = 64;
    float* out_idx    = out;
    float* out_val    = out + BB * k;
    float* out_logits = out + 2 * BB * k;

    detect_et<<<1, 1>>>(etypes);
    prep_query<<<BB, HID>>>(center, Wq, bq);
    prep_small<<<1, HID>>>(W1, Wt, Ws, bt, bs, bc, b1, Ee);
    prep_cvec<<<BB, HID>>>(W1);
    prep_wf<<<TEXT, HID>>>(Wc, W1);
    main_kernel<<<MROWS/64, 256>>>(emb, center, maskv, etypes, yd, cs, W2, b2, out_logits);
    topk_kernel<<<BB, 512>>>(out_logits, out_idx, out_val, k);
}